// round 8
// baseline (speedup 1.0000x reference)
#include <cuda_runtime.h>
#include <math_constants.h>

// GaussianVector_box — single-kernel store streamer, params amortized 2x.
// 128-thread CTAs; each thread owns TWO float4s per row (cols t, t+128), so the
// per-box param math (floors, bounds, fast-rcp) is computed half as often per
// stored byte. 4x STG.128 streaming stores per thread. 268 MB f32 writes.
// Output: [vector_x (B*N*1024)] ++ [vector_y (B*N*1024)].

#define OUT_W 1024
#define OUT_H 1024

__device__ __forceinline__ float4 gauss4(float c0, float ul, float br,
                                         float ctr, float k)
{
    float4 v = make_float4(0.f, 0.f, 0.f, 0.f);
    if ((c0 + 3.0f) >= ul && c0 < br) {
        #pragma unroll
        for (int j = 0; j < 4; ++j) {
            float p = c0 + (float)j;
            if (p >= ul && p < br) {
                float d = p - ctr;
                float e = __expf(d * d * k);
                if (j == 0) v.x = e; else if (j == 1) v.y = e;
                else if (j == 2) v.z = e; else v.w = e;
            }
        }
    }
    return v;
}

__global__ __launch_bounds__(128, 16)
void gv_box_kernel(const float* __restrict__ centers,
                   const float* __restrict__ whs,
                   float* __restrict__ out_x,
                   float* __restrict__ out_y)
{
    const int bn = blockIdx.x;
    const int t  = threadIdx.x;

    // Broadcast loads (uniform address per CTA -> single sector, L1/L2 hit).
    const float2 c  = __ldg(((const float2*)centers) + bn);
    const float2 wh = __ldg(((const float2*)whs) + bn);

    // ks = floor(W/2)*2 - 1 ; r = (ks-1)/2 = floor(W/2) - 1 (exact)
    const float rw = floorf(wh.x * 0.5f) - 1.0f;
    const float rh = floorf(wh.y * 0.5f) - 1.0f;
    // s = floor(r/3), exact for integer r via the +0.5 trick (no IEEE div)
    const float sw = floorf((rw + 0.5f) * (1.0f / 3.0f));
    const float sh = floorf((rh + 0.5f) * (1.0f / 3.0f));

    const bool zero_box = (c.x + c.y + wh.x + wh.y) == 0.0f;

    // SCALE = 1 ; astype(int32) truncates toward zero
    const float x = truncf(c.x);
    const float y = truncf(c.y);

    float ul0 = x - rw, ul1 = y - rh;
    float br0 = x + rw + 1.0f, br1 = y + rh + 1.0f;

    const bool in_ul = (ul0 >= 0.0f) & (ul0 <= (float)OUT_W) &
                       (ul1 >= 0.0f) & (ul1 <= (float)OUT_H);
    const bool in_br = (br0 >= 0.0f) & (br0 <= (float)OUT_W) &
                       (br1 >= 0.0f) & (br1 <= (float)OUT_H);

    const bool active = (!zero_box) & (sw != 0.0f) & (sh != 0.0f) & (in_ul | in_br);

    if (!active) {   // empty windows -> all lanes write zero, no exp evaluated
        ul0 = CUDART_INF_F;  br0 = -CUDART_INF_F;
        ul1 = CUDART_INF_F;  br1 = -CUDART_INF_F;
    }

    // -1/(2 sigma^2) via fast reciprocal (only consumed inside valid windows)
    const float kx = __fdividef(-0.5f, sw * sw);
    const float ky = __fdividef(-0.5f, sh * sh);

    const float c0 = (float)(t << 2);        // cols [t*4, t*4+3]
    const float c1 = c0 + 512.0f;            // cols [(t+128)*4 ...]

    const float4 vx0 = gauss4(c0, ul0, br0, x, kx);
    const float4 vx1 = gauss4(c1, ul0, br0, x, kx);
    const float4 vy0 = gauss4(c0, ul1, br1, y, ky);
    const float4 vy1 = gauss4(c1, ul1, br1, y, ky);

    // Streaming (evict-first) 128-bit stores; warp-contiguous 512B runs.
    float4* px = ((float4*)(out_x + (size_t)bn * OUT_W)) + t;
    float4* py = ((float4*)(out_y + (size_t)bn * OUT_H)) + t;
    __stcs(px,       vx0);
    __stcs(px + 128, vx1);
    __stcs(py,       vy0);
    __stcs(py + 128, vy1);
}

extern "C" void kernel_launch(void* const* d_in, const int* in_sizes, int n_in,
                              void* d_out, int out_size)
{
    const float* centers = (const float*)d_in[0];  // [B,N,2]
    const float* whs     = (const float*)d_in[1];  // [B,N,2]
    float* out = (float*)d_out;

    const int BN = in_sizes[0] / 2;                // 128*256 = 32768
    float* out_x = out;
    float* out_y = out + (size_t)BN * OUT_W;

    gv_box_kernel<<<BN, 128>>>(centers, whs, out_x, out_y);
}

// round 10
// speedup vs baseline: 1.0172x; 1.0172x over previous
#include <cuda_runtime.h>
#include <math_constants.h>

// GaussianVector_box — single-kernel store streamer.
// 256-thread CTAs, TWO boxes per CTA (half-CTA each), each thread owns two
// float4s per row -> param math amortized 2x per stored byte AND half the CTA
// count of the 128-thread variant. 4x STG.128 streaming stores per thread.
// Output: [vector_x (B*N*1024)] ++ [vector_y (B*N*1024)], f32, 268 MB writes.

#define OUT_W 1024
#define OUT_H 1024

__device__ __forceinline__ float4 gauss4(float c0, float ul, float br,
                                         float ctr, float k)
{
    float4 v = make_float4(0.f, 0.f, 0.f, 0.f);
    if ((c0 + 3.0f) >= ul && c0 < br) {
        #pragma unroll
        for (int j = 0; j < 4; ++j) {
            float p = c0 + (float)j;
            if (p >= ul && p < br) {
                float d = p - ctr;
                float e = __expf(d * d * k);
                if (j == 0) v.x = e; else if (j == 1) v.y = e;
                else if (j == 2) v.z = e; else v.w = e;
            }
        }
    }
    return v;
}

__global__ __launch_bounds__(256, 8)
void gv_box_kernel(const float* __restrict__ centers,
                   const float* __restrict__ whs,
                   float* __restrict__ out_x,
                   float* __restrict__ out_y)
{
    const int bn = (blockIdx.x << 1) + (threadIdx.x >> 7);  // 2 boxes per CTA
    const int t  = threadIdx.x & 127;                       // 0..127 within box

    // Broadcast loads (uniform address per half-CTA -> single sector, L1/L2 hit).
    const float2 c  = __ldg(((const float2*)centers) + bn);
    const float2 wh = __ldg(((const float2*)whs) + bn);

    // ks = floor(W/2)*2 - 1 ; r = (ks-1)/2 = floor(W/2) - 1 (exact)
    const float rw = floorf(wh.x * 0.5f) - 1.0f;
    const float rh = floorf(wh.y * 0.5f) - 1.0f;
    // s = floor(r/3), exact for integer r via the +0.5 trick (no IEEE div)
    const float sw = floorf((rw + 0.5f) * (1.0f / 3.0f));
    const float sh = floorf((rh + 0.5f) * (1.0f / 3.0f));

    const bool zero_box = (c.x + c.y + wh.x + wh.y) == 0.0f;

    // SCALE = 1 ; astype(int32) truncates toward zero
    const float x = truncf(c.x);
    const float y = truncf(c.y);

    float ul0 = x - rw, ul1 = y - rh;
    float br0 = x + rw + 1.0f, br1 = y + rh + 1.0f;

    const bool in_ul = (ul0 >= 0.0f) & (ul0 <= (float)OUT_W) &
                       (ul1 >= 0.0f) & (ul1 <= (float)OUT_H);
    const bool in_br = (br0 >= 0.0f) & (br0 <= (float)OUT_W) &
                       (br1 >= 0.0f) & (br1 <= (float)OUT_H);

    const bool active = (!zero_box) & (sw != 0.0f) & (sh != 0.0f) & (in_ul | in_br);

    if (!active) {   // empty windows -> all lanes write zero, no exp evaluated
        ul0 = CUDART_INF_F;  br0 = -CUDART_INF_F;
        ul1 = CUDART_INF_F;  br1 = -CUDART_INF_F;
    }

    // -1/(2 sigma^2) via fast reciprocal (only consumed inside valid windows)
    const float kx = __fdividef(-0.5f, sw * sw);
    const float ky = __fdividef(-0.5f, sh * sh);

    const float c0 = (float)(t << 2);        // cols [t*4, t*4+3]
    const float c1 = c0 + 512.0f;            // cols [(t+128)*4 ...]

    const float4 vx0 = gauss4(c0, ul0, br0, x, kx);
    const float4 vx1 = gauss4(c1, ul0, br0, x, kx);
    const float4 vy0 = gauss4(c0, ul1, br1, y, ky);
    const float4 vy1 = gauss4(c1, ul1, br1, y, ky);

    // Streaming (evict-first) 128-bit stores; warp-contiguous 512B runs.
    float4* px = ((float4*)(out_x + (size_t)bn * OUT_W)) + t;
    float4* py = ((float4*)(out_y + (size_t)bn * OUT_H)) + t;
    __stcs(px,       vx0);
    __stcs(px + 128, vx1);
    __stcs(py,       vy0);
    __stcs(py + 128, vy1);
}

extern "C" void kernel_launch(void* const* d_in, const int* in_sizes, int n_in,
                              void* d_out, int out_size)
{
    const float* centers = (const float*)d_in[0];  // [B,N,2]
    const float* whs     = (const float*)d_in[1];  // [B,N,2]
    float* out = (float*)d_out;

    const int BN = in_sizes[0] / 2;                // 128*256 = 32768
    float* out_x = out;
    float* out_y = out + (size_t)BN * OUT_W;

    gv_box_kernel<<<BN / 2, 256>>>(centers, whs, out_x, out_y);
}